// round 14
// baseline (speedup 1.0000x reference)
#include <cuda_runtime.h>
#include <cuda_bf16.h>

#define FEAT 64
#define EPR 136             // edges per 16-lane group -> 736 blocks (one wave)
#define ROWS_PER_BLOCK 16   // 256 threads / 16 lanes
#define THREADS 256

// Single-kernel weighted segment-sum over sorted segment_ids, bias fused,
// NO atomics ("owner extends" protocol):
//  - the row where a segment's first edge lies owns the WHOLE segment and
//    keeps accumulating past its chunk end until the segment ends;
//  - rows whose chunk starts mid-segment skip that head run (seg scan only;
//    attn/feats of those edges are read exactly once, by the owner);
//  - every flush is a plain idempotent STG.128 of acc+bias;
//  - gaps between consecutive segment ids get plain bias stores.
__global__ void __launch_bounds__(THREADS)
segsum_kernel(const float4* __restrict__ feats,   // [E,16] float4 view of [E,64]
              const float*  __restrict__ attn,    // [E]
              const int*    __restrict__ seg,     // [E] sorted
              float* __restrict__ out,            // [N,64]
              const float4* __restrict__ bias4,   // [16]
              int n_edges, int n_nodes) {
    int row  = blockIdx.x * ROWS_PER_BLOCK + (threadIdx.x >> 4);
    int lane = threadIdx.x & 15;

    int e0 = row * EPR;
    if (e0 >= n_edges) return;
    int e_end = e0 + EPR;
    if (e_end > n_edges) e_end = n_edges;

    float4 bia = __ldg(&bias4[lane]);
    int head = __ldg(&seg[e0]);

    // leading empty nodes [0, seg[0]) — only the very first row
    if (e0 == 0) {
        for (int m = 0; m < head; ++m)
            ((float4*)(out + (size_t)m * FEAT))[lane] = bia;
    }

    int e = e0;
    // skip the head run if it started in a previous chunk (owner handles it)
    if (e0 > 0 && __ldg(&seg[e0 - 1]) == head) {
        for (;;) {
            int s0 = (e + 0 < e_end) ? __ldg(&seg[e + 0]) : -1;
            int s1 = (e + 1 < e_end) ? __ldg(&seg[e + 1]) : -1;
            int s2 = (e + 2 < e_end) ? __ldg(&seg[e + 2]) : -1;
            int s3 = (e + 3 < e_end) ? __ldg(&seg[e + 3]) : -1;
            bool c0 = (s0 == head);
            bool c1 = c0 && (s1 == head);
            bool c2 = c1 && (s2 == head);
            bool c3 = c2 && (s3 == head);
            int m = (int)c0 + (int)c1 + (int)c2 + (int)c3;
            e += m;
            if (m < 4) break;
        }
        if (e >= e_end) return;   // whole chunk inside a foreign segment
    }

    float4 acc = make_float4(0.f, 0.f, 0.f, 0.f);
    int cur = __ldg(&seg[e]);     // first run we own (starts at e)

    // flush cur with bias, then fill gap up to NEXTID with bias stores
    #define FLUSH_GAP(NEXTID)                                                  \
    do {                                                                       \
        float4 v = make_float4(acc.x + bia.x, acc.y + bia.y,                   \
                               acc.z + bia.z, acc.w + bia.w);                  \
        ((float4*)(out + (size_t)cur * FEAT))[lane] = v;                       \
        for (int m_ = cur + 1; m_ < (NEXTID); ++m_)                            \
            ((float4*)(out + (size_t)m_ * FEAT))[lane] = bia;                  \
    } while (0)

    #define STEP(S, A, F)                                                      \
    do {                                                                       \
        if (S != cur) {                                                        \
            FLUSH_GAP(S);                                                      \
            acc = make_float4(0.f, 0.f, 0.f, 0.f);                             \
            cur = S;                                                           \
        }                                                                      \
        acc.x = fmaf(A, F.x, acc.x); acc.y = fmaf(A, F.y, acc.y);              \
        acc.z = fmaf(A, F.z, acc.z); acc.w = fmaf(A, F.w, acc.w);              \
    } while (0)

    // main loop over our chunk (front-batched loads, proven shape)
    for (; e + 4 <= e_end; e += 4) {
        int   s0 = __ldg(&seg[e + 0]), s1 = __ldg(&seg[e + 1]);
        int   s2 = __ldg(&seg[e + 2]), s3 = __ldg(&seg[e + 3]);
        float a0 = __ldg(&attn[e + 0]), a1 = __ldg(&attn[e + 1]);
        float a2 = __ldg(&attn[e + 2]), a3 = __ldg(&attn[e + 3]);
        float4 f0 = __ldg(&feats[(size_t)(e + 0) * 16 + lane]);
        float4 f1 = __ldg(&feats[(size_t)(e + 1) * 16 + lane]);
        float4 f2 = __ldg(&feats[(size_t)(e + 2) * 16 + lane]);
        float4 f3 = __ldg(&feats[(size_t)(e + 3) * 16 + lane]);

        STEP(s0, a0, f0);
        STEP(s1, a1, f1);
        STEP(s2, a2, f2);
        STEP(s3, a3, f3);
    }
    for (; e < e_end; ++e) {
        int   s = __ldg(&seg[e]);
        float a = __ldg(&attn[e]);
        float4 f = __ldg(&feats[(size_t)e * 16 + lane]);
        STEP(s, a, f);
    }
    #undef STEP

    // extension: we own `cur`; keep accumulating past e_end until it ends
    int e2 = e_end;
    int next_id = n_nodes;        // id of the first edge after our last run
    while (e2 < n_edges) {
        int s0 = (e2 + 0 < n_edges) ? __ldg(&seg[e2 + 0]) : -1;
        int s1 = (e2 + 1 < n_edges) ? __ldg(&seg[e2 + 1]) : -1;
        int s2 = (e2 + 2 < n_edges) ? __ldg(&seg[e2 + 2]) : -1;
        int s3 = (e2 + 3 < n_edges) ? __ldg(&seg[e2 + 3]) : -1;
        bool c0 = (s0 == cur);
        bool c1 = c0 && (s1 == cur);
        bool c2 = c1 && (s2 == cur);
        bool c3 = c2 && (s3 == cur);

        if (c0) {
            float  a0 = __ldg(&attn[e2 + 0]);
            float4 f0 = __ldg(&feats[(size_t)(e2 + 0) * 16 + lane]);
            acc.x = fmaf(a0, f0.x, acc.x); acc.y = fmaf(a0, f0.y, acc.y);
            acc.z = fmaf(a0, f0.z, acc.z); acc.w = fmaf(a0, f0.w, acc.w);
        }
        if (c1) {
            float  a1 = __ldg(&attn[e2 + 1]);
            float4 f1 = __ldg(&feats[(size_t)(e2 + 1) * 16 + lane]);
            acc.x = fmaf(a1, f1.x, acc.x); acc.y = fmaf(a1, f1.y, acc.y);
            acc.z = fmaf(a1, f1.z, acc.z); acc.w = fmaf(a1, f1.w, acc.w);
        }
        if (c2) {
            float  a2 = __ldg(&attn[e2 + 2]);
            float4 f2 = __ldg(&feats[(size_t)(e2 + 2) * 16 + lane]);
            acc.x = fmaf(a2, f2.x, acc.x); acc.y = fmaf(a2, f2.y, acc.y);
            acc.z = fmaf(a2, f2.z, acc.z); acc.w = fmaf(a2, f2.w, acc.w);
        }
        if (c3) {
            float  a3 = __ldg(&attn[e2 + 3]);
            float4 f3 = __ldg(&feats[(size_t)(e2 + 3) * 16 + lane]);
            acc.x = fmaf(a3, f3.x, acc.x); acc.y = fmaf(a3, f3.y, acc.y);
            acc.z = fmaf(a3, f3.z, acc.z); acc.w = fmaf(a3, f3.w, acc.w);
        }

        int m = (int)c0 + (int)c1 + (int)c2 + (int)c3;
        e2 += m;
        if (m < 4) {
            // first non-matching edge (if any) gives the next segment id
            if (e2 < n_edges) next_id = (m == 0) ? s0 : (m == 1) ? s1
                                        : (m == 2) ? s2 : s3;
            break;
        }
    }

    // final flush of our last run + trailing gap fill
    FLUSH_GAP(next_id);
    #undef FLUSH_GAP
}

extern "C" void kernel_launch(void* const* d_in, const int* in_sizes, int n_in,
                              void* d_out, int out_size) {
    // metadata order: nodes[0] (unused), neighbor_feats[1], attention[2],
    //                 bias[3], segment_ids[4]
    const float* feats = (const float*)d_in[1];
    const float* attn  = (const float*)d_in[2];
    const float* bias  = (const float*)d_in[3];
    const int*   seg   = (const int*)d_in[4];
    float* out = (float*)d_out;

    int n_edges = in_sizes[2];          // attention element count = E
    int n_nodes = out_size / FEAT;      // N
    int n_rows  = (n_edges + EPR - 1) / EPR;
    int blocks  = (n_rows + ROWS_PER_BLOCK - 1) / ROWS_PER_BLOCK;

    segsum_kernel<<<blocks, THREADS>>>((const float4*)feats, attn, seg, out,
                                       (const float4*)bias, n_edges, n_nodes);
}

// round 15
// speedup vs baseline: 1.0214x; 1.0214x over previous
#include <cuda_runtime.h>
#include <cuda_bf16.h>

#define FEAT 64
#define EPR 136             // edges per 16-lane group -> 736 blocks (one wave)
#define ROWS_PER_BLOCK 16   // 256 threads / 16 lanes
#define THREADS 256

// Grid-barrier state. Invariant at every launch entry: g_cnt == 0.
// Sense flips exactly once per launch; last arriver resets g_cnt.
// -> deterministic & graph-replay safe.
__device__ unsigned int g_cnt = 0;
__device__ volatile unsigned int g_sense = 0;

// Fused kernel:
//   Phase 0: zero exactly the nodes that receive atomicAdd flushes (segment
//            crosses a chunk boundary: seg[b*EPR-1] == seg[b*EPR]).
//   Grid barrier (all 736 CTAs co-resident: 5 CTAs/SM x 148 = 740 capacity,
//            guaranteed by __launch_bounds__(256,5) -> regs <= 51).
//   Phase 1: R13 segsum — front-batched loads, bias-fused plain STG.128 for
//            runs contained in one chunk, atomicAdd for boundary-crossing
//            segments (owner adds bias once), bias stores for empty nodes.
__global__ void __launch_bounds__(THREADS, 5)
segsum_fused_kernel(const float4* __restrict__ feats,  // [E,16] view of [E,64]
                    const float*  __restrict__ attn,   // [E]
                    const int*    __restrict__ seg,    // [E] sorted
                    float* __restrict__ out,           // [N,64]
                    const float4* __restrict__ bias4,  // [16]
                    int n_edges, int n_nodes, int n_rows) {
    int row  = blockIdx.x * ROWS_PER_BLOCK + (threadIdx.x >> 4);
    int lane = threadIdx.x & 15;

    // ---- Phase 0: zero future atomic targets (one boundary per group) ----
    unsigned int s_local = 0;
    if (threadIdx.x == 0) s_local = g_sense;

    if (row >= 1 && row < n_rows) {
        int e = row * EPR;
        if (e < n_edges) {
            int s = __ldg(&seg[e]);
            if (__ldg(&seg[e - 1]) == s)
                ((float4*)out)[(size_t)s * 16 + lane] =
                    make_float4(0.f, 0.f, 0.f, 0.f);
        }
    }

    // ---- Grid barrier (sense-reversing; all CTAs resident) ----
    __threadfence();
    __syncthreads();
    if (threadIdx.x == 0) {
        unsigned int old = atomicAdd(&g_cnt, 1u);
        if (old == gridDim.x - 1) {
            g_cnt = 0;              // all arrived; restore invariant
            __threadfence();
            g_sense = s_local ^ 1u; // release
        } else {
            while (g_sense == s_local) { }
        }
    }
    __syncthreads();
    __threadfence();

    // ---- Phase 1: segsum (R13 verbatim) ----
    int e0 = row * EPR;
    if (e0 >= n_edges) return;
    int e_end = e0 + EPR;
    if (e_end > n_edges) e_end = n_edges;

    float4 bia = __ldg(&bias4[lane]);
    float4 acc = make_float4(0.f, 0.f, 0.f, 0.f);
    int  cur   = __ldg(&seg[e0]);
    bool first = true;   // still inside the chunk's first run
    bool owned_head = (e0 == 0) || (__ldg(&seg[e0 - 1]) != cur);

    // leading empty nodes [0, seg[0]) — only the very first group
    if (e0 == 0) {
        for (int m = 0; m < cur; ++m)
            ((float4*)(out + (size_t)m * FEAT))[lane] = bia;
    }

    #define STEP(S, A, F)                                                      \
    do {                                                                       \
        if (S != cur) {                                                        \
            if (first && !owned_head) {                                        \
                /* continuation of a segment started earlier: raw partial */   \
                float* o = out + (size_t)cur * FEAT + lane * 4;                \
                atomicAdd(o + 0, acc.x); atomicAdd(o + 1, acc.y);              \
                atomicAdd(o + 2, acc.z); atomicAdd(o + 3, acc.w);              \
            } else {                                                           \
                /* run started and ended here: sole writer, bias fused */      \
                float4 v = make_float4(acc.x + bia.x, acc.y + bia.y,           \
                                       acc.z + bia.z, acc.w + bia.w);          \
                ((float4*)(out + (size_t)cur * FEAT))[lane] = v;               \
            }                                                                  \
            for (int m = cur + 1; m < S; ++m)                                  \
                ((float4*)(out + (size_t)m * FEAT))[lane] = bia;               \
            first = false;                                                     \
            acc = make_float4(0.f, 0.f, 0.f, 0.f);                             \
            cur = S;                                                           \
        }                                                                      \
        acc.x = fmaf(A, F.x, acc.x); acc.y = fmaf(A, F.y, acc.y);              \
        acc.z = fmaf(A, F.z, acc.z); acc.w = fmaf(A, F.w, acc.w);              \
    } while (0)

    int e = e0;
    for (; e + 4 <= e_end; e += 4) {
        // ---- load phase: independent LDGs, no control flow between them ----
        int   s0 = __ldg(&seg[e + 0]), s1 = __ldg(&seg[e + 1]);
        int   s2 = __ldg(&seg[e + 2]), s3 = __ldg(&seg[e + 3]);
        float a0 = __ldg(&attn[e + 0]), a1 = __ldg(&attn[e + 1]);
        float a2 = __ldg(&attn[e + 2]), a3 = __ldg(&attn[e + 3]);
        float4 f0 = __ldg(&feats[(size_t)(e + 0) * 16 + lane]);
        float4 f1 = __ldg(&feats[(size_t)(e + 1) * 16 + lane]);
        float4 f2 = __ldg(&feats[(size_t)(e + 2) * 16 + lane]);
        float4 f3 = __ldg(&feats[(size_t)(e + 3) * 16 + lane]);

        // ---- process phase ----
        STEP(s0, a0, f0);
        STEP(s1, a1, f1);
        STEP(s2, a2, f2);
        STEP(s3, a3, f3);
    }
    for (; e < e_end; ++e) {
        int   s = __ldg(&seg[e]);
        float a = __ldg(&attn[e]);
        float4 f = __ldg(&feats[(size_t)e * 16 + lane]);
        STEP(s, a, f);
    }
    #undef STEP

    // tail flush
    bool has_next = (e_end < n_edges);
    int  next_s   = has_next ? __ldg(&seg[e_end]) : n_nodes;
    bool tail_shared = has_next && (next_s == cur);

    if (first && !owned_head) {
        // whole chunk sits inside a larger segment: raw continuation partial
        float* o = out + (size_t)cur * FEAT + lane * 4;
        atomicAdd(o + 0, acc.x); atomicAdd(o + 1, acc.y);
        atomicAdd(o + 2, acc.z); atomicAdd(o + 3, acc.w);
    } else if (tail_shared) {
        // segment STARTS here and crosses out: owner contributes bias once
        float* o = out + (size_t)cur * FEAT + lane * 4;
        atomicAdd(o + 0, acc.x + bia.x); atomicAdd(o + 1, acc.y + bia.y);
        atomicAdd(o + 2, acc.z + bia.z); atomicAdd(o + 3, acc.w + bia.w);
    } else {
        // segment starts and ends within this chunk: sole writer
        float4 v = make_float4(acc.x + bia.x, acc.y + bia.y,
                               acc.z + bia.z, acc.w + bia.w);
        ((float4*)(out + (size_t)cur * FEAT))[lane] = v;
    }

    // trailing empty nodes up to the next chunk's first segment (or N)
    for (int m = cur + 1; m < next_s; ++m)
        ((float4*)(out + (size_t)m * FEAT))[lane] = bia;
}

extern "C" void kernel_launch(void* const* d_in, const int* in_sizes, int n_in,
                              void* d_out, int out_size) {
    // metadata order: nodes[0] (unused), neighbor_feats[1], attention[2],
    //                 bias[3], segment_ids[4]
    const float* feats = (const float*)d_in[1];
    const float* attn  = (const float*)d_in[2];
    const float* bias  = (const float*)d_in[3];
    const int*   seg   = (const int*)d_in[4];
    float* out = (float*)d_out;

    int n_edges = in_sizes[2];          // attention element count = E
    int n_nodes = out_size / FEAT;      // N
    int n_rows  = (n_edges + EPR - 1) / EPR;
    int blocks  = (n_rows + ROWS_PER_BLOCK - 1) / ROWS_PER_BLOCK;

    segsum_fused_kernel<<<blocks, THREADS>>>((const float4*)feats, attn, seg,
                                             out, (const float4*)bias,
                                             n_edges, n_nodes, n_rows);
}